// round 7
// baseline (speedup 1.0000x reference)
#include <cuda_runtime.h>
#include <cuda_bf16.h>
#include <cstdint>

// Problem constants (fixed by the dataset).
#define N_NODES 50000
#define D 128
#define CAP 64            // slots per row bucket

typedef unsigned long long ull;

// Device-global scratch (no allocation).
__device__ float g_support[(size_t)N_NODES * D];        // x @ W (25.6 MB)
__device__ ull   g_bins[(size_t)N_NODES * CAP];         // packed (val,col) per row
__device__ int   g_cnt[N_NODES];                        // per-row degree (reset by gather)
__device__ __nv_bfloat16 g_Bt_hi[256 * 128];            // [n][k]; n 0-127: W^T, 128-255: Wr^T
__device__ __nv_bfloat16 g_Bt_lo[256 * 128];            // bf16 residuals

// ----------------------------- helpers -------------------------------------
__device__ __forceinline__ uint32_t packbf(float lo, float hi) {
    uint32_t r;
    asm("cvt.rn.bf16x2.f32 %0, %1, %2;" : "=r"(r) : "f"(hi), "f"(lo));
    return r;
}
__device__ __forceinline__ float bfround(float v) {
    return __bfloat162float(__float2bfloat16_rn(v));
}
__device__ __forceinline__ void mma_bf16(float* c, const uint32_t* a, const uint32_t* b) {
    asm volatile(
        "mma.sync.aligned.m16n8k16.row.col.f32.bf16.bf16.f32 "
        "{%0,%1,%2,%3}, {%4,%5,%6,%7}, {%8,%9}, {%0,%1,%2,%3};"
        : "+f"(c[0]), "+f"(c[1]), "+f"(c[2]), "+f"(c[3])
        : "r"(a[0]), "r"(a[1]), "r"(a[2]), "r"(a[3]), "r"(b[0]), "r"(b[1]));
}

// ---------------------------------------------------------------------------
// Kernel 1 (fused): blocks [0, ebl) bin edges into row buckets; the last 16
// blocks transpose + bf16-split W / Wr into g_Bt_{hi,lo}  (B = [W^T ; Wr^T]).
// ---------------------------------------------------------------------------
__global__ void __launch_bounds__(256)
gcn_bin_prep(const int*   __restrict__ erow,
             const int*   __restrict__ ecol,
             const float* __restrict__ eval,
             const float* __restrict__ W,
             const float* __restrict__ Wr,
             int e_count, int ebl)
{
    if ((int)blockIdx.x >= ebl) {
        int pb   = blockIdx.x - ebl;        // 0..15
        int mat  = pb >> 3;                 // 0 = W, 1 = Wr
        int part = pb & 7;                  // 1/8 of the 128x128 matrix
        const float* src = mat ? Wr : W;
        // iterate in (n,k) order so destination writes coalesce
        for (int i = 0; i < 8; i++) {
            int j  = part * 2048 + i * 256 + threadIdx.x;
            int nn = j >> 7, k = j & 127;
            float v = src[k * D + nn];      // W[k][nn]
            float h = bfround(v);
            float l = v - h;
            g_Bt_hi[(mat * 128 + nn) * 128 + k] = __float2bfloat16_rn(h);
            g_Bt_lo[(mat * 128 + nn) * 128 + k] = __float2bfloat16_rn(l);
        }
        return;
    }
    int e = blockIdx.x * 256 + threadIdx.x;
    if (e >= e_count) return;
    int   r = __ldg(erow + e);
    int   c = __ldg(ecol + e);
    float v = __ldg(eval + e);
    int idx = atomicAdd(&g_cnt[r], 1);
    if (idx < CAP) {
        ull p = ((ull)__float_as_uint(v) << 32) | (unsigned)c;
        g_bins[(size_t)r * CAP + idx] = p;
    }
}

// ---------------------------------------------------------------------------
// Kernel 2: HMMA bf16 3-pass GEMM (hi*hi + hi*lo + lo*hi, fp32 accum).
//   blockIdx.y == 0:  g_support = x @ W
//   blockIdx.y == 1:  out       = x @ W_root   (initializes d_out)
// CTA tile 128x128, 8 warps (4 M x 2 N), warp tile 32x64, K chunk 32.
// SMEM rows stride 80 B (20 words == 4 mod 32 per 4-row step -> conflict-free
// fragment loads across all 32 lanes).
// ---------------------------------------------------------------------------
#define SA_HI 0
#define SA_LO 10240
#define SB_HI 20480
#define SB_LO 30720
#define SROW  80

__global__ void __launch_bounds__(256, 2)
gcn_gemm_mma(const float* __restrict__ x, float* __restrict__ out, int n)
{
    __shared__ __align__(16) char sm[40960];
    const int tid  = threadIdx.x;
    const int lane = tid & 31;
    const int wid  = tid >> 5;
    const int wm   = (wid & 3) * 32;      // warp M offset in CTA tile
    const int wn   = (wid >> 2) * 64;     // warp N offset
    const int row0 = blockIdx.x * 128;
    const int by   = blockIdx.y;

    const int qrow = lane >> 2;           // 0..7
    const int qk   = (lane & 3) * 4;      // byte offset of k pair

    float c[2][8][4];
    #pragma unroll
    for (int mt = 0; mt < 2; mt++)
        #pragma unroll
        for (int nt = 0; nt < 8; nt++)
            #pragma unroll
            for (int i = 0; i < 4; i++) c[mt][nt][i] = 0.f;

    const __nv_bfloat16* bth = g_Bt_hi + (size_t)(by * 128) * 128;
    const __nv_bfloat16* btl = g_Bt_lo + (size_t)(by * 128) * 128;

    for (int ch = 0; ch < 4; ch++) {
        const int kc = ch * 32;

        // ---- stage A (x rows, bf16 hi/lo split): 128 rows x 32 k
        #pragma unroll
        for (int i = 0; i < 4; i++) {
            int f = tid + i * 256;
            int r = f >> 3, g = f & 7;
            int gr = row0 + r;
            float4 v = make_float4(0.f, 0.f, 0.f, 0.f);
            if (gr < n) v = *(const float4*)&x[(size_t)gr * D + kc + g * 4];
            uint32_t h01 = packbf(v.x, v.y);
            uint32_t h23 = packbf(v.z, v.w);
            uint32_t l01 = packbf(v.x - bfround(v.x), v.y - bfround(v.y));
            uint32_t l23 = packbf(v.z - bfround(v.z), v.w - bfround(v.w));
            *(uint2*)(sm + SA_HI + r * SROW + g * 8) = make_uint2(h01, h23);
            *(uint2*)(sm + SA_LO + r * SROW + g * 8) = make_uint2(l01, l23);
        }
        // ---- stage B (pre-split W^T/Wr^T): 128 n-rows x 32 k, plain copy
        #pragma unroll
        for (int i = 0; i < 2; i++) {
            int f = tid + i * 256;            // 0..511
            int nr = f >> 2, q = f & 3;
            const char* sh = (const char*)bth + ((size_t)nr * 128 + kc) * 2 + q * 16;
            const char* sl = (const char*)btl + ((size_t)nr * 128 + kc) * 2 + q * 16;
            *(uint4*)(sm + SB_HI + nr * SROW + q * 16) = *(const uint4*)sh;
            *(uint4*)(sm + SB_LO + nr * SROW + q * 16) = *(const uint4*)sl;
        }
        __syncthreads();

        #pragma unroll
        for (int ks = 0; ks < 2; ks++) {
            const int kb = ks * 32 + qk;      // byte offset within 64B k-row
            uint32_t ah[2][4], al[2][4];
            #pragma unroll
            for (int mt = 0; mt < 2; mt++) {
                const char* ba = sm + SA_HI + (wm + mt * 16 + qrow) * SROW + kb;
                ah[mt][0] = *(const uint32_t*)(ba);
                ah[mt][1] = *(const uint32_t*)(ba + 8 * SROW);
                ah[mt][2] = *(const uint32_t*)(ba + 16);
                ah[mt][3] = *(const uint32_t*)(ba + 8 * SROW + 16);
                const char* bb = sm + SA_LO + (wm + mt * 16 + qrow) * SROW + kb;
                al[mt][0] = *(const uint32_t*)(bb);
                al[mt][1] = *(const uint32_t*)(bb + 8 * SROW);
                al[mt][2] = *(const uint32_t*)(bb + 16);
                al[mt][3] = *(const uint32_t*)(bb + 8 * SROW + 16);
            }
            #pragma unroll
            for (int ntg = 0; ntg < 2; ntg++) {
                uint32_t bh[4][2], bl[4][2];
                #pragma unroll
                for (int t = 0; t < 4; t++) {
                    const char* bb = sm + SB_HI + (wn + (ntg * 4 + t) * 8 + qrow) * SROW + kb;
                    bh[t][0] = *(const uint32_t*)(bb);
                    bh[t][1] = *(const uint32_t*)(bb + 16);
                    const char* bc = sm + SB_LO + (wn + (ntg * 4 + t) * 8 + qrow) * SROW + kb;
                    bl[t][0] = *(const uint32_t*)(bc);
                    bl[t][1] = *(const uint32_t*)(bc + 16);
                }
                #pragma unroll
                for (int t = 0; t < 4; t++) {
                    int nt = ntg * 4 + t;
                    #pragma unroll
                    for (int mt = 0; mt < 2; mt++) {
                        mma_bf16(c[mt][nt], ah[mt], bh[t]);   // hi*hi
                        mma_bf16(c[mt][nt], ah[mt], bl[t]);   // hi*lo
                        mma_bf16(c[mt][nt], al[mt], bh[t]);   // lo*hi
                    }
                }
            }
        }
        __syncthreads();
    }

    // ---- epilogue
    float* dst = by ? out : g_support;
    #pragma unroll
    for (int mt = 0; mt < 2; mt++) {
        int r1 = row0 + wm + mt * 16 + qrow;
        int r2 = r1 + 8;
        #pragma unroll
        for (int nt = 0; nt < 8; nt++) {
            int col = wn + nt * 8 + (lane & 3) * 2;
            if (r1 < n)
                *(float2*)&dst[(size_t)r1 * D + col] = make_float2(c[mt][nt][0], c[mt][nt][1]);
            if (r2 < n)
                *(float2*)&dst[(size_t)r2 * D + col] = make_float2(c[mt][nt][2], c[mt][nt][3]);
        }
    }
}

// ---------------------------------------------------------------------------
// Kernel 3: atomic-free gather, warp per row. Resets g_cnt for the next
// replay (globals start zeroed; each launch sequence restores the zero state).
// ---------------------------------------------------------------------------
__global__ void __launch_bounds__(256)
gcn_gather_kernel(float* __restrict__ out, int n)
{
    const int lane = threadIdx.x & 31;
    const int row  = (blockIdx.x * blockDim.x + threadIdx.x) >> 5;
    if (row >= n) return;

    int m = g_cnt[row];
    if (lane == 0) g_cnt[row] = 0;
    if (m > CAP) m = CAP;
    const ull* bp = g_bins + (size_t)row * CAP;

    float4 acc = make_float4(0.f, 0.f, 0.f, 0.f);

    for (int base = 0; base < m; base += 32) {
        int k = m - base; if (k > 32) k = 32;
        ull p = 0;
        if (lane < k) p = __ldg(bp + base + lane);

        int i = 0;
        for (; i + 4 <= k; i += 4) {
            float4 s0, s1, s2, s3;
            float  v0, v1, v2, v3;
            { ull pi = __shfl_sync(0xffffffffu, p, i + 0);
              v0 = __uint_as_float((unsigned)(pi >> 32));
              s0 = __ldg((const float4*)(g_support + (size_t)(unsigned)(pi & 0xffffffffu) * D) + lane); }
            { ull pi = __shfl_sync(0xffffffffu, p, i + 1);
              v1 = __uint_as_float((unsigned)(pi >> 32));
              s1 = __ldg((const float4*)(g_support + (size_t)(unsigned)(pi & 0xffffffffu) * D) + lane); }
            { ull pi = __shfl_sync(0xffffffffu, p, i + 2);
              v2 = __uint_as_float((unsigned)(pi >> 32));
              s2 = __ldg((const float4*)(g_support + (size_t)(unsigned)(pi & 0xffffffffu) * D) + lane); }
            { ull pi = __shfl_sync(0xffffffffu, p, i + 3);
              v3 = __uint_as_float((unsigned)(pi >> 32));
              s3 = __ldg((const float4*)(g_support + (size_t)(unsigned)(pi & 0xffffffffu) * D) + lane); }
            acc.x += v0 * s0.x; acc.y += v0 * s0.y; acc.z += v0 * s0.z; acc.w += v0 * s0.w;
            acc.x += v1 * s1.x; acc.y += v1 * s1.y; acc.z += v1 * s1.z; acc.w += v1 * s1.w;
            acc.x += v2 * s2.x; acc.y += v2 * s2.y; acc.z += v2 * s2.z; acc.w += v2 * s2.w;
            acc.x += v3 * s3.x; acc.y += v3 * s3.y; acc.z += v3 * s3.z; acc.w += v3 * s3.w;
        }
        for (; i < k; i++) {
            ull pi = __shfl_sync(0xffffffffu, p, i);
            float v = __uint_as_float((unsigned)(pi >> 32));
            float4 s = __ldg((const float4*)(g_support + (size_t)(unsigned)(pi & 0xffffffffu) * D) + lane);
            acc.x += v * s.x; acc.y += v * s.y; acc.z += v * s.z; acc.w += v * s.w;
        }
    }

    float4* op = (float4*)(out + (size_t)row * D) + lane;
    float4 o = *op;                          // root term from GEMM
    o.x += acc.x; o.y += acc.y; o.z += acc.z; o.w += acc.w;
    *op = o;
}

// ---------------------------------------------------------------------------
extern "C" void kernel_launch(void* const* d_in, const int* in_sizes, int n_in,
                              void* d_out, int out_size)
{
    const float* x   = (const float*)d_in[0];   // [N, 128]
    const int*   er  = (const int*)  d_in[1];   // [E]
    const int*   ec  = (const int*)  d_in[2];   // [E]
    const float* ev  = (const float*)d_in[3];   // [E]
    const float* W   = (const float*)d_in[4];   // [128, 128]
    const float* Wr  = (const float*)d_in[5];   // [128, 128]
    float*       out = (float*)d_out;           // [N, 128]

    const int n = in_sizes[0] / D;
    const int e = in_sizes[1];

    // 1) bin edges + prep (transpose & bf16-split W, Wr) — fused
    int ebl = (e + 255) / 256;
    gcn_bin_prep<<<ebl + 16, 256>>>(er, ec, ev, W, Wr, e, ebl);

    // 2) HMMA bf16 3-pass GEMM: g_support = x@W (y=0), out = x@Wr (y=1)
    dim3 grid(391, 2);
    gcn_gemm_mma<<<grid, 256>>>(x, out, n);

    // 3) atomic-free gather (also resets g_cnt for next replay)
    gcn_gather_kernel<<<(n * 32 + 255) / 256, 256>>>(out, n);
}

// round 8
// speedup vs baseline: 1.0077x; 1.0077x over previous
#include <cuda_runtime.h>
#include <cuda_bf16.h>
#include <cstdint>

// Problem constants (fixed by the dataset).
#define N_NODES 50000
#define D 128
#define CAP 64            // slots per row bucket

typedef unsigned long long ull;

// Device-global scratch (no allocation).
__device__ float g_support[(size_t)N_NODES * D];        // x @ W (25.6 MB)
__device__ ull   g_bins[(size_t)N_NODES * CAP];         // packed (val,col) per row
__device__ int   g_cnt[N_NODES];                        // per-row degree (reset by gather)
__device__ __nv_bfloat16 g_Bt_hi[256 * 128];            // [n][k]; n 0-127: W^T, 128-255: Wr^T
__device__ __nv_bfloat16 g_Bt_lo[256 * 128];            // bf16 residuals

// ----------------------------- helpers -------------------------------------
__device__ __forceinline__ uint32_t packbf(float lo, float hi) {
    uint32_t r;
    asm("cvt.rn.bf16x2.f32 %0, %1, %2;" : "=r"(r) : "f"(hi), "f"(lo));
    return r;
}
__device__ __forceinline__ float bfround(float v) {
    return __bfloat162float(__float2bfloat16_rn(v));
}
// NOTE: no "volatile" — ptxas must be free to reorder/interleave HMMAs.
__device__ __forceinline__ void mma_bf16(float* c, const uint32_t* a, const uint32_t* b) {
    asm("mma.sync.aligned.m16n8k16.row.col.f32.bf16.bf16.f32 "
        "{%0,%1,%2,%3}, {%4,%5,%6,%7}, {%8,%9}, {%0,%1,%2,%3};"
        : "+f"(c[0]), "+f"(c[1]), "+f"(c[2]), "+f"(c[3])
        : "r"(a[0]), "r"(a[1]), "r"(a[2]), "r"(a[3]), "r"(b[0]), "r"(b[1]));
}

// ---------------------------------------------------------------------------
// Kernel 1 (fused): blocks [0, ebl) bin edges into row buckets; the last 16
// blocks transpose + bf16-split W / Wr into g_Bt_{hi,lo}  (B = [W^T ; Wr^T]).
// ---------------------------------------------------------------------------
__global__ void __launch_bounds__(256)
gcn_bin_prep(const int*   __restrict__ erow,
             const int*   __restrict__ ecol,
             const float* __restrict__ eval,
             const float* __restrict__ W,
             const float* __restrict__ Wr,
             int e_count, int ebl)
{
    if ((int)blockIdx.x >= ebl) {
        int pb   = blockIdx.x - ebl;        // 0..15
        int mat  = pb >> 3;                 // 0 = W, 1 = Wr
        int part = pb & 7;                  // 1/8 of the 128x128 matrix
        const float* src = mat ? Wr : W;
        #pragma unroll
        for (int i = 0; i < 8; i++) {
            int j  = part * 2048 + i * 256 + threadIdx.x;
            int nn = j >> 7, k = j & 127;
            float v = src[k * D + nn];      // W[k][nn]
            float h = bfround(v);
            float l = v - h;
            g_Bt_hi[(mat * 128 + nn) * 128 + k] = __float2bfloat16_rn(h);
            g_Bt_lo[(mat * 128 + nn) * 128 + k] = __float2bfloat16_rn(l);
        }
        return;
    }
    int e = blockIdx.x * 256 + threadIdx.x;
    if (e >= e_count) return;
    int   r = __ldg(erow + e);
    int   c = __ldg(ecol + e);
    float v = __ldg(eval + e);
    int idx = atomicAdd(&g_cnt[r], 1);
    if (idx < CAP) {
        ull p = ((ull)__float_as_uint(v) << 32) | (unsigned)c;
        g_bins[(size_t)r * CAP + idx] = p;
    }
}

// ---------------------------------------------------------------------------
// Kernel 2: HMMA bf16 3-pass GEMM (hi*hi + hi*lo + lo*hi, fp32 accum).
//   blockIdx.y == 0:  g_support = x @ W
//   blockIdx.y == 1:  out       = x @ W_root   (initializes d_out)
// CTA tile 128x128, 8 warps (4 M x 2 N), warp tile 32x64, K chunk 32.
// Pass-major mma ordering: 16 independent accumulators between any reuse.
// ---------------------------------------------------------------------------
#define SA_HI 0
#define SA_LO 10240
#define SB_HI 20480
#define SB_LO 30720
#define SROW  80

__global__ void __launch_bounds__(256, 2)
gcn_gemm_mma(const float* __restrict__ x, float* __restrict__ out, int n)
{
    __shared__ __align__(16) char sm[40960];
    const int tid  = threadIdx.x;
    const int lane = tid & 31;
    const int wid  = tid >> 5;
    const int wm   = (wid & 3) * 32;      // warp M offset in CTA tile
    const int wn   = (wid >> 2) * 64;     // warp N offset
    const int row0 = blockIdx.x * 128;
    const int by   = blockIdx.y;

    const int qrow = lane >> 2;           // 0..7
    const int qk   = (lane & 3) * 4;      // byte offset of k pair

    float c[2][8][4];
    #pragma unroll
    for (int mt = 0; mt < 2; mt++)
        #pragma unroll
        for (int nt = 0; nt < 8; nt++)
            #pragma unroll
            for (int i = 0; i < 4; i++) c[mt][nt][i] = 0.f;

    const __nv_bfloat16* bth = g_Bt_hi + (size_t)(by * 128) * 128;
    const __nv_bfloat16* btl = g_Bt_lo + (size_t)(by * 128) * 128;

    for (int ch = 0; ch < 4; ch++) {
        const int kc = ch * 32;

        // ---- stage A (x rows, bf16 hi/lo split): 128 rows x 32 k
        #pragma unroll
        for (int i = 0; i < 4; i++) {
            int f = tid + i * 256;
            int r = f >> 3, g = f & 7;
            int gr = row0 + r;
            float4 v = make_float4(0.f, 0.f, 0.f, 0.f);
            if (gr < n) v = *(const float4*)&x[(size_t)gr * D + kc + g * 4];
            uint32_t h01 = packbf(v.x, v.y);
            uint32_t h23 = packbf(v.z, v.w);
            uint32_t l01 = packbf(v.x - bfround(v.x), v.y - bfround(v.y));
            uint32_t l23 = packbf(v.z - bfround(v.z), v.w - bfround(v.w));
            *(uint2*)(sm + SA_HI + r * SROW + g * 8) = make_uint2(h01, h23);
            *(uint2*)(sm + SA_LO + r * SROW + g * 8) = make_uint2(l01, l23);
        }
        // ---- stage B (pre-split W^T/Wr^T): 128 n-rows x 32 k, plain copy
        #pragma unroll
        for (int i = 0; i < 2; i++) {
            int f = tid + i * 256;            // 0..511
            int nr = f >> 2, q = f & 3;
            const char* sh = (const char*)bth + ((size_t)nr * 128 + kc) * 2 + q * 16;
            const char* sl = (const char*)btl + ((size_t)nr * 128 + kc) * 2 + q * 16;
            *(uint4*)(sm + SB_HI + nr * SROW + q * 16) = *(const uint4*)sh;
            *(uint4*)(sm + SB_LO + nr * SROW + q * 16) = *(const uint4*)sl;
        }
        __syncthreads();

        #pragma unroll
        for (int ks = 0; ks < 2; ks++) {
            const int kb = ks * 32 + qk;      // byte offset within 64B k-row
            uint32_t ah[2][4], al[2][4];
            #pragma unroll
            for (int mt = 0; mt < 2; mt++) {
                const char* ba = sm + SA_HI + (wm + mt * 16 + qrow) * SROW + kb;
                ah[mt][0] = *(const uint32_t*)(ba);
                ah[mt][1] = *(const uint32_t*)(ba + 8 * SROW);
                ah[mt][2] = *(const uint32_t*)(ba + 16);
                ah[mt][3] = *(const uint32_t*)(ba + 8 * SROW + 16);
                const char* bb = sm + SA_LO + (wm + mt * 16 + qrow) * SROW + kb;
                al[mt][0] = *(const uint32_t*)(bb);
                al[mt][1] = *(const uint32_t*)(bb + 8 * SROW);
                al[mt][2] = *(const uint32_t*)(bb + 16);
                al[mt][3] = *(const uint32_t*)(bb + 8 * SROW + 16);
            }
            // pass-major: consecutive mmas hit 16 distinct accumulators
            #pragma unroll
            for (int pass = 0; pass < 3; pass++) {
                const uint32_t (&af)[2][4] = (pass == 2) ? al : ah;
                const int boff = (pass == 1) ? SB_LO : SB_HI;
                #pragma unroll
                for (int nt = 0; nt < 8; nt++) {
                    uint32_t b[2];
                    const char* bb = sm + boff + (wn + nt * 8 + qrow) * SROW + kb;
                    b[0] = *(const uint32_t*)(bb);
                    b[1] = *(const uint32_t*)(bb + 16);
                    mma_bf16(c[0][nt], af[0], b);
                    mma_bf16(c[1][nt], af[1], b);
                }
            }
        }
        __syncthreads();
    }

    // ---- epilogue
    float* dst = by ? out : g_support;
    #pragma unroll
    for (int mt = 0; mt < 2; mt++) {
        int r1 = row0 + wm + mt * 16 + qrow;
        int r2 = r1 + 8;
        #pragma unroll
        for (int nt = 0; nt < 8; nt++) {
            int col = wn + nt * 8 + (lane & 3) * 2;
            if (r1 < n)
                *(float2*)&dst[(size_t)r1 * D + col] = make_float2(c[mt][nt][0], c[mt][nt][1]);
            if (r2 < n)
                *(float2*)&dst[(size_t)r2 * D + col] = make_float2(c[mt][nt][2], c[mt][nt][3]);
        }
    }
}

// ---------------------------------------------------------------------------
// Kernel 3: atomic-free gather, warp per row. Resets g_cnt for the next
// replay (globals start zeroed; each launch sequence restores the zero state).
// ---------------------------------------------------------------------------
__global__ void __launch_bounds__(256)
gcn_gather_kernel(float* __restrict__ out, int n)
{
    const int lane = threadIdx.x & 31;
    const int row  = (blockIdx.x * blockDim.x + threadIdx.x) >> 5;
    if (row >= n) return;

    int m = g_cnt[row];
    if (lane == 0) g_cnt[row] = 0;
    if (m > CAP) m = CAP;
    const ull* bp = g_bins + (size_t)row * CAP;

    float4 acc = make_float4(0.f, 0.f, 0.f, 0.f);

    for (int base = 0; base < m; base += 32) {
        int k = m - base; if (k > 32) k = 32;
        ull p = 0;
        if (lane < k) p = __ldg(bp + base + lane);

        int i = 0;
        for (; i + 4 <= k; i += 4) {
            float4 s0, s1, s2, s3;
            float  v0, v1, v2, v3;
            { ull pi = __shfl_sync(0xffffffffu, p, i + 0);
              v0 = __uint_as_float((unsigned)(pi >> 32));
              s0 = __ldg((const float4*)(g_support + (size_t)(unsigned)(pi & 0xffffffffu) * D) + lane); }
            { ull pi = __shfl_sync(0xffffffffu, p, i + 1);
              v1 = __uint_as_float((unsigned)(pi >> 32));
              s1 = __ldg((const float4*)(g_support + (size_t)(unsigned)(pi & 0xffffffffu) * D) + lane); }
            { ull pi = __shfl_sync(0xffffffffu, p, i + 2);
              v2 = __uint_as_float((unsigned)(pi >> 32));
              s2 = __ldg((const float4*)(g_support + (size_t)(unsigned)(pi & 0xffffffffu) * D) + lane); }
            { ull pi = __shfl_sync(0xffffffffu, p, i + 3);
              v3 = __uint_as_float((unsigned)(pi >> 32));
              s3 = __ldg((const float4*)(g_support + (size_t)(unsigned)(pi & 0xffffffffu) * D) + lane); }
            acc.x += v0 * s0.x; acc.y += v0 * s0.y; acc.z += v0 * s0.z; acc.w += v0 * s0.w;
            acc.x += v1 * s1.x; acc.y += v1 * s1.y; acc.z += v1 * s1.z; acc.w += v1 * s1.w;
            acc.x += v2 * s2.x; acc.y += v2 * s2.y; acc.z += v2 * s2.z; acc.w += v2 * s2.w;
            acc.x += v3 * s3.x; acc.y += v3 * s3.y; acc.z += v3 * s3.z; acc.w += v3 * s3.w;
        }
        for (; i < k; i++) {
            ull pi = __shfl_sync(0xffffffffu, p, i);
            float v = __uint_as_float((unsigned)(pi >> 32));
            float4 s = __ldg((const float4*)(g_support + (size_t)(unsigned)(pi & 0xffffffffu) * D) + lane);
            acc.x += v * s.x; acc.y += v * s.y; acc.z += v * s.z; acc.w += v * s.w;
        }
    }

    float4* op = (float4*)(out + (size_t)row * D) + lane;
    float4 o = *op;                          // root term from GEMM
    o.x += acc.x; o.y += acc.y; o.z += acc.z; o.w += acc.w;
    *op = o;
}

// ---------------------------------------------------------------------------
extern "C" void kernel_launch(void* const* d_in, const int* in_sizes, int n_in,
                              void* d_out, int out_size)
{
    const float* x   = (const float*)d_in[0];   // [N, 128]
    const int*   er  = (const int*)  d_in[1];   // [E]
    const int*   ec  = (const int*)  d_in[2];   // [E]
    const float* ev  = (const float*)d_in[3];   // [E]
    const float* W   = (const float*)d_in[4];   // [128, 128]
    const float* Wr  = (const float*)d_in[5];   // [128, 128]
    float*       out = (float*)d_out;           // [N, 128]

    const int n = in_sizes[0] / D;
    const int e = in_sizes[1];

    // 1) bin edges + prep (transpose & bf16-split W, Wr) — fused
    int ebl = (e + 255) / 256;
    gcn_bin_prep<<<ebl + 16, 256>>>(er, ec, ev, W, Wr, e, ebl);

    // 2) HMMA bf16 3-pass GEMM: g_support = x@W (y=0), out = x@Wr (y=1)
    dim3 grid(391, 2);
    gcn_gemm_mma<<<grid, 256>>>(x, out, n);

    // 3) atomic-free gather (also resets g_cnt for next replay)
    gcn_gather_kernel<<<(n * 32 + 255) / 256, 256>>>(out, n);
}